// round 1
// baseline (speedup 1.0000x reference)
#include <cuda_runtime.h>
#include <cstdint>
#include <cstddef>

// Problem dims
#define B_SZ 16
#define T_SZ 2048
#define K_IN 1024          // INP_DIM == MODEL_DIM
#define D_MODEL 1024
#define MLP 2048
#define NCLS 1000

// GEMM tiling for kernel A
#define BM 128             // t-rows per block (== scan chunk length)
#define BND 64             // d-channels per block (outputs 2*BND cols: f|z)
#define BK 32
#define APITCH 36          // smem pitch for A tile (floats)
#define WPITCH 136         // smem pitch for W tile (floats)
#define NCHUNK (T_SZ / BM) // 16 chunks per batch

// -------- scratch (device globals; no allocation allowed) --------
__device__ float g_chunkA[B_SZ * NCHUNK * D_MODEL];
__device__ float g_chunkC[B_SZ * NCHUNK * D_MODEL];
__device__ float g_cT[B_SZ * D_MODEL];
__device__ float g_h[B_SZ * D_MODEL];
__device__ float g_n0[B_SZ * MLP];
__device__ float g_n1[B_SZ * MLP];
__device__ float g_opre[B_SZ * D_MODEL];
__device__ float g_n0pre[B_SZ * MLP];
__device__ float g_n1pre[B_SZ * MLP];
__device__ float g_outpre[B_SZ * NCLS];

// -------- helpers --------
__device__ __forceinline__ uint32_t f2tf32(float x) {
    uint32_t u;
    asm("cvt.rna.tf32.f32 %0, %1;" : "=r"(u) : "f"(x));
    return u;
}

__device__ __forceinline__ void mma_tf32(float c[4],
                                         uint32_t a0, uint32_t a1, uint32_t a2, uint32_t a3,
                                         uint32_t b0, uint32_t b1) {
    asm volatile(
        "mma.sync.aligned.m16n8k8.row.col.f32.tf32.tf32.f32 "
        "{%0,%1,%2,%3}, {%4,%5,%6,%7}, {%8,%9}, {%0,%1,%2,%3};\n"
        : "+f"(c[0]), "+f"(c[1]), "+f"(c[2]), "+f"(c[3])
        : "r"(a0), "r"(a1), "r"(a2), "r"(a3), "r"(b0), "r"(b1));
}

__device__ __forceinline__ float sigmoidf_(float x) {
    return 1.0f / (1.0f + __expf(-x));
}

// =====================================================================
// Kernel A: fused GEMM (tf32 mma) + activations + chunk-local scan.
// Grid: (D_MODEL/BND = 16, B*NCHUNK = 256). Block: 256 threads (8 warps).
// Output tile per block: BM x (2*BND) = 128 x 128 (fh | zh).
// =====================================================================
__global__ void __launch_bounds__(256)
gemm_scan_kernel(const float* __restrict__ x, const float* __restrict__ Wp,
                 const float* __restrict__ bp) {
    extern __shared__ float sm[];
    float* As = sm;                       // [BM][APITCH]   (18432 B)
    float* Ws = sm + BM * APITCH;         // [BK][WPITCH]   (17408 B)
    // Epilogue reuse (after sync):
    float* fS = sm;                       // [BM][64]       (32768 B)
    float* zS = sm + BM * 64;             // [BM][64]       (32768 B)

    const int dt = blockIdx.x;            // d-tile 0..15
    const int bc = blockIdx.y;            // b*16 + chunk
    const int b = bc >> 4;
    const int chunk = bc & 15;
    const int d0 = dt * BND;

    const float* xbase = x + ((size_t)b * T_SZ + (size_t)chunk * BM) * K_IN;

    const int tid = threadIdx.x;
    const int lane = tid & 31;
    const int wid = tid >> 5;
    const int wm = (wid >> 2) * 64;       // warp m offset (0 or 64)
    const int wn = (wid & 3) * 32;        // warp n offset (0,32,64,96)
    const int g = lane >> 2;              // groupID
    const int tg = lane & 3;              // thread-in-group

    float acc[4][4][4];
#pragma unroll
    for (int mi = 0; mi < 4; mi++)
#pragma unroll
        for (int ni = 0; ni < 4; ni++)
#pragma unroll
            for (int r = 0; r < 4; r++) acc[mi][ni][r] = 0.0f;

    for (int kk = 0; kk < K_IN; kk += BK) {
        __syncthreads();
        // ---- load A tile: 128 rows x 32 k, as tf32 bit patterns ----
#pragma unroll
        for (int i = 0; i < 4; i++) {
            int idx = tid + i * 256;          // 0..1023 float4 slots
            int row = idx >> 3;
            int kq = (idx & 7) * 4;
            float4 v = *(const float4*)(xbase + (size_t)row * K_IN + kk + kq);
            float* dst = &As[row * APITCH + kq];
            dst[0] = __uint_as_float(f2tf32(v.x));
            dst[1] = __uint_as_float(f2tf32(v.y));
            dst[2] = __uint_as_float(f2tf32(v.z));
            dst[3] = __uint_as_float(f2tf32(v.w));
        }
        // ---- load W tile: 32 k-rows x (64 f-cols + 64 z-cols) ----
#pragma unroll
        for (int i = 0; i < 4; i++) {
            int idx = tid + i * 256;          // 0..1023 float4 slots
            int k = idx >> 5;
            int q = idx & 31;
            int seg = q >> 4;                 // 0: f cols, 1: z cols
            int col = (q & 15) * 4;
            int gcol = d0 + col + (seg ? D_MODEL : 0);
            float4 v = *(const float4*)(Wp + (size_t)(kk + k) * 3072 + gcol);
            float* dst = &Ws[k * WPITCH + seg * 64 + col];
            dst[0] = __uint_as_float(f2tf32(v.x));
            dst[1] = __uint_as_float(f2tf32(v.y));
            dst[2] = __uint_as_float(f2tf32(v.z));
            dst[3] = __uint_as_float(f2tf32(v.w));
        }
        __syncthreads();

#pragma unroll
        for (int ks = 0; ks < BK / 8; ks++) {
            const int k0 = ks * 8;
            uint32_t a[4][4], bb[4][2];
#pragma unroll
            for (int mi = 0; mi < 4; mi++) {
                int r0 = wm + mi * 16;
                a[mi][0] = __float_as_uint(As[(r0 + g) * APITCH + k0 + tg]);
                a[mi][1] = __float_as_uint(As[(r0 + g + 8) * APITCH + k0 + tg]);
                a[mi][2] = __float_as_uint(As[(r0 + g) * APITCH + k0 + tg + 4]);
                a[mi][3] = __float_as_uint(As[(r0 + g + 8) * APITCH + k0 + tg + 4]);
            }
#pragma unroll
            for (int ni = 0; ni < 4; ni++) {
                int c0 = wn + ni * 8 + g;
                bb[ni][0] = __float_as_uint(Ws[(k0 + tg) * WPITCH + c0]);
                bb[ni][1] = __float_as_uint(Ws[(k0 + tg + 4) * WPITCH + c0]);
            }
#pragma unroll
            for (int mi = 0; mi < 4; mi++)
#pragma unroll
                for (int ni = 0; ni < 4; ni++)
                    mma_tf32(acc[mi][ni], a[mi][0], a[mi][1], a[mi][2], a[mi][3],
                             bb[ni][0], bb[ni][1]);
        }
    }

    __syncthreads();
    // ---- write accumulators (raw fh / zh) to smem ----
#pragma unroll
    for (int mi = 0; mi < 4; mi++) {
#pragma unroll
        for (int ni = 0; ni < 4; ni++) {
            int nc = wn + ni * 8 + tg * 2;    // 0..126, warp-uniform half
            float* buf = (nc < 64) ? fS : zS;
            int col = nc & 63;
            int r = wm + mi * 16 + g;
            *(float2*)&buf[r * 64 + col] = make_float2(acc[mi][ni][0], acc[mi][ni][1]);
            *(float2*)&buf[(r + 8) * 64 + col] = make_float2(acc[mi][ni][2], acc[mi][ni][3]);
        }
    }
    __syncthreads();

    // ---- chunk-local scan: c_t = f_t*c + z_t ; A = prod f ----
    // 256 threads = 64 d-columns x 4 t-subchunks of 32.
    __shared__ float sA[4][64];
    __shared__ float sC[4][64];
    {
        const int dd = tid & 63;
        const int j = tid >> 6;
        const float bpf = bp[d0 + dd];
        const float bpz = bp[D_MODEL + d0 + dd];
        float A = 1.0f, C = 0.0f;
#pragma unroll 4
        for (int i = 0; i < 32; i++) {
            int t = j * 32 + i;
            float fh = fS[t * 64 + dd] + bpf;
            float zh = zS[t * 64 + dd] + bpz;
            float f = sigmoidf_(fh);
            float z = (1.0f - f) * tanhf(zh);
            C = C * f + z;
            A = A * f;
        }
        sA[j][dd] = A;
        sC[j][dd] = C;
    }
    __syncthreads();
    if (tid < 64) {
        float A = sA[0][tid], C = sC[0][tid];
#pragma unroll
        for (int j = 1; j < 4; j++) {
            C = C * sA[j][tid] + sC[j][tid];
            A = A * sA[j][tid];
        }
        size_t o = ((size_t)b * NCHUNK + chunk) * D_MODEL + d0 + tid;
        g_chunkA[o] = A;
        g_chunkC[o] = C;
    }
}

// =====================================================================
// Kernel B: combine chunk pairs -> c_T.  Grid: (D_MODEL/256, B)
// =====================================================================
__global__ void combine_kernel() {
    int b = blockIdx.y;
    int d = blockIdx.x * 256 + threadIdx.x;
    float c = 0.0f;
#pragma unroll
    for (int ch = 0; ch < NCHUNK; ch++) {
        size_t o = ((size_t)b * NCHUNK + ch) * D_MODEL + d;
        c = c * g_chunkA[o] + g_chunkC[o];
    }
    g_cT[b * D_MODEL + d] = c;
}

// =====================================================================
// Tail: split-K vector(16) x matrix accumulate with atomicAdd.
// Grid: (ceil(N/256), K/128). Block: 256 threads.
// =====================================================================
#define KS 128
__global__ void __launch_bounds__(256)
vmacc_kernel(const float* __restrict__ in, size_t inStride,
             const float* __restrict__ W, int ldw, int colOff,
             float* __restrict__ pre, int K, int N) {
    __shared__ float s_in[B_SZ * KS];
    const int tid = threadIdx.x;
    const int bn = blockIdx.x * 256;
    const int ks = blockIdx.y * KS;

    for (int i = tid; i < B_SZ * KS; i += 256) {
        int bb = i / KS, k = i % KS;
        s_in[i] = in[(size_t)bb * inStride + ks + k];
    }
    __syncthreads();

    int n = bn + tid;
    if (n >= N) return;

    float acc[B_SZ];
#pragma unroll
    for (int bb = 0; bb < B_SZ; bb++) acc[bb] = 0.0f;

    for (int k = 0; k < KS; k++) {
        float w = W[(size_t)(ks + k) * ldw + colOff + n];
#pragma unroll
        for (int bb = 0; bb < B_SZ; bb++) acc[bb] += s_in[bb * KS + k] * w;
    }
#pragma unroll
    for (int bb = 0; bb < B_SZ; bb++) atomicAdd(&pre[(size_t)bb * N + n], acc[bb]);
}

// -------- zero + finalize kernels --------
__global__ void zero_kernel() {
    int i = blockIdx.x * 256 + threadIdx.x;
    if (i < B_SZ * D_MODEL) g_opre[i] = 0.0f;
    if (i < B_SZ * MLP) { g_n0pre[i] = 0.0f; g_n1pre[i] = 0.0f; }
    if (i < B_SZ * NCLS) g_outpre[i] = 0.0f;
}

__global__ void final_oh_kernel(const float* __restrict__ bp) {
    int i = blockIdx.x * 256 + threadIdx.x;
    if (i < B_SZ * D_MODEL) {
        int d = i & (D_MODEL - 1);
        float o = 1.0f / (1.0f + __expf(-(g_opre[i] + bp[2 * D_MODEL + d])));
        g_h[i] = g_cT[i] * o;
    }
}

__global__ void final_relu0_kernel(const float* __restrict__ bias) {
    int i = blockIdx.x * 256 + threadIdx.x;
    if (i < B_SZ * MLP) {
        int n = i & (MLP - 1);
        float v = g_n0pre[i] + bias[n];
        g_n0[i] = v > 0.0f ? v : 0.0f;
    }
}

__global__ void final_relu1_kernel(const float* __restrict__ bias) {
    int i = blockIdx.x * 256 + threadIdx.x;
    if (i < B_SZ * MLP) {
        int n = i & (MLP - 1);
        float v = g_n1pre[i] + bias[n];
        g_n1[i] = v > 0.0f ? v : 0.0f;
    }
}

__global__ void final_out_kernel(const float* __restrict__ b2, float* __restrict__ out) {
    int i = blockIdx.x * 256 + threadIdx.x;
    if (i < B_SZ * NCLS) {
        int n = i % NCLS;
        out[i] = g_outpre[i] + b2[n];
    }
}

// =====================================================================
extern "C" void kernel_launch(void* const* d_in, const int* in_sizes, int n_in,
                              void* d_out, int out_size) {
    const float* x  = (const float*)d_in[0];
    const float* Wp = (const float*)d_in[1];
    const float* bp = (const float*)d_in[2];
    const float* W0 = (const float*)d_in[3];
    const float* b0 = (const float*)d_in[4];
    const float* W1 = (const float*)d_in[5];
    const float* b1 = (const float*)d_in[6];
    const float* W2 = (const float*)d_in[7];
    const float* b2 = (const float*)d_in[8];
    float* out = (float*)d_out;

    cudaFuncSetAttribute(gemm_scan_kernel,
                         cudaFuncAttributeMaxDynamicSharedMemorySize, 65536);

    float *p_h, *p_n0, *p_n1, *p_opre, *p_n0pre, *p_n1pre, *p_outpre;
    cudaGetSymbolAddress((void**)&p_h, g_h);
    cudaGetSymbolAddress((void**)&p_n0, g_n0);
    cudaGetSymbolAddress((void**)&p_n1, g_n1);
    cudaGetSymbolAddress((void**)&p_opre, g_opre);
    cudaGetSymbolAddress((void**)&p_n0pre, g_n0pre);
    cudaGetSymbolAddress((void**)&p_n1pre, g_n1pre);
    cudaGetSymbolAddress((void**)&p_outpre, g_outpre);

    // 1. zero accumulation scratch
    zero_kernel<<<(B_SZ * MLP + 255) / 256, 256>>>();

    // 2. fused f/z GEMM + chunk scan
    gemm_scan_kernel<<<dim3(D_MODEL / BND, B_SZ * NCHUNK), 256, 65536>>>(x, Wp, bp);

    // 3. combine chunks -> c_T
    combine_kernel<<<dim3(D_MODEL / 256, B_SZ), 256>>>();

    // 4. o-projection at t = T-1 (uses x last row), then h = c_T * sigmoid(oh + bp_o)
    vmacc_kernel<<<dim3(D_MODEL / 256, K_IN / KS), 256>>>(
        x + (size_t)(T_SZ - 1) * K_IN, (size_t)T_SZ * K_IN,
        Wp, 3 * D_MODEL, 2 * D_MODEL, p_opre, K_IN, D_MODEL);
    final_oh_kernel<<<(B_SZ * D_MODEL + 255) / 256, 256>>>(bp);

    // 5. MLP layer 0: relu(h @ W0 + b0)
    vmacc_kernel<<<dim3(MLP / 256, D_MODEL / KS), 256>>>(
        p_h, D_MODEL, W0, MLP, 0, p_n0pre, D_MODEL, MLP);
    final_relu0_kernel<<<(B_SZ * MLP + 255) / 256, 256>>>(b0);

    // 6. MLP layer 1: relu(n0 @ W1 + b1)
    vmacc_kernel<<<dim3(MLP / 256, MLP / KS), 256>>>(
        p_n0, MLP, W1, MLP, 0, p_n1pre, MLP, MLP);
    final_relu1_kernel<<<(B_SZ * MLP + 255) / 256, 256>>>(b1);

    // 7. output layer: n1 @ W2 + b2
    vmacc_kernel<<<dim3((NCLS + 255) / 256, MLP / KS), 256>>>(
        p_n1, MLP, W2, NCLS, 0, p_outpre, MLP, NCLS);
    final_out_kernel<<<(B_SZ * NCLS + 255) / 256, 256>>>(b2, out);
}

// round 5
// speedup vs baseline: 1.7279x; 1.7279x over previous
#include <cuda_runtime.h>
#include <cuda_fp16.h>
#include <cstdint>
#include <cstddef>

// ---------------- problem dims ----------------
#define B_SZ 16
#define T_SZ 2048
#define K_IN 1024
#define D_MODEL 1024
#define MLP 2048
#define NCLS 1000

// ---------------- GEMM tiling ----------------
#define BM 128               // t-rows per block (scan chunk)
#define NCOL 128             // output cols per block: 64 f | 64 z
#define BK 64                // k per pipeline chunk
#define NCH (K_IN / BK)      // 16
#define NCHUNK (T_SZ / BM)   // 16

#define AP 72                // smem pitch in halves (144B, 16B-aligned)
#define ABYTES (BM * AP * 2)     // 18432
#define STAGE (2 * ABYTES)       // 36864 (A + W)
#define SMEM_TOTAL (2 * STAGE)   // 73728
#define EPITCH 66            // epilogue float pitch

// ---------------- scratch ----------------
__device__ __align__(16) __half g_xh[(size_t)B_SZ * T_SZ * K_IN];   // 64 MB
__device__ __align__(16) __half g_wh[2048 * K_IN];                  // 4 MB, [n][k]
__device__ float g_chunkA[B_SZ * NCHUNK * D_MODEL];
__device__ float g_chunkC[B_SZ * NCHUNK * D_MODEL];
__device__ float g_cT[B_SZ * D_MODEL];
__device__ float g_h[B_SZ * D_MODEL];
__device__ float g_n0[B_SZ * MLP];
__device__ float g_n1[B_SZ * MLP];
__device__ float g_opre[B_SZ * D_MODEL];
__device__ float g_n0pre[B_SZ * MLP];
__device__ float g_n1pre[B_SZ * MLP];
__device__ float g_outpre[B_SZ * NCLS];

// ---------------- helpers ----------------
__device__ __forceinline__ uint32_t smem_u32(const void* p) {
    uint32_t a;
    asm("{ .reg .u64 t; cvta.to.shared.u64 t, %1; cvt.u32.u64 %0, t; }" : "=r"(a) : "l"(p));
    return a;
}
__device__ __forceinline__ void cpa16(uint32_t dst, const void* src) {
    asm volatile("cp.async.cg.shared.global [%0], [%1], 16;\n" :: "r"(dst), "l"(src));
}
#define CP_COMMIT() asm volatile("cp.async.commit_group;" ::: "memory")
#define CP_WAIT(n) asm volatile("cp.async.wait_group %0;" :: "n"(n) : "memory")

__device__ __forceinline__ void mma_f16(float c[4],
                                        uint32_t a0, uint32_t a1, uint32_t a2, uint32_t a3,
                                        uint32_t b0, uint32_t b1) {
    asm volatile(
        "mma.sync.aligned.m16n8k16.row.col.f32.f16.f16.f32 "
        "{%0,%1,%2,%3}, {%4,%5,%6,%7}, {%8,%9}, {%0,%1,%2,%3};\n"
        : "+f"(c[0]), "+f"(c[1]), "+f"(c[2]), "+f"(c[3])
        : "r"(a0), "r"(a1), "r"(a2), "r"(a3), "r"(b0), "r"(b1));
}

__device__ __forceinline__ float sigmoidf_(float x) { return 1.0f / (1.0f + __expf(-x)); }

// =====================================================================
// Conversion kernels
// =====================================================================
__global__ void convx_kernel(const float* __restrict__ x) {
    size_t n4 = (size_t)B_SZ * T_SZ * K_IN / 4;
    for (size_t i = blockIdx.x * 256 + threadIdx.x; i < n4; i += (size_t)gridDim.x * 256) {
        float4 v = ((const float4*)x)[i];
        __half2* o = (__half2*)g_xh;
        o[i * 2] = __floats2half2_rn(v.x, v.y);
        o[i * 2 + 1] = __floats2half2_rn(v.z, v.w);
    }
}

// transpose Wp[:, 0:2048] -> g_wh[n][k] fp16
__global__ void __launch_bounds__(256) convw_kernel(const float* __restrict__ Wp) {
    __shared__ float tile[64][65];
    int k0 = blockIdx.x * 64;
    int n0 = blockIdx.y * 64;
    int tid = threadIdx.x;
#pragma unroll
    for (int i = 0; i < 16; i++) {
        int idx = tid + i * 256;
        int r = idx >> 6, c = idx & 63;
        tile[r][c] = Wp[(size_t)(k0 + r) * 3072 + n0 + c];
    }
    __syncthreads();
#pragma unroll
    for (int i = 0; i < 16; i++) {
        int idx = tid + i * 256;
        int r = idx >> 6, c = idx & 63;
        g_wh[(size_t)(n0 + r) * K_IN + k0 + c] = __float2half(tile[c][r]);
    }
}

// =====================================================================
// Fused fp16 mma.sync GEMM + activations + chunk scan.
// Grid: (16 d-tiles, 256 bc). Block: 256 threads (8 warps, 2x4 warp grid).
// Output tile: 128 t-rows x (64 f | 64 z) cols.
// =====================================================================
__global__ void __launch_bounds__(256)
gemm_scan_kernel(const float* __restrict__ bp) {
    extern __shared__ char smem[];
    const uint32_t sb = smem_u32(smem);

    const int dt = blockIdx.x;            // d-tile 0..15 (64 channels each)
    const int bc = blockIdx.y;
    const int b = bc >> 4;
    const int chunk = bc & 15;
    const int d0 = dt * 64;

    const int tid = threadIdx.x;
    const int lane = tid & 31;
    const int wid = tid >> 5;
    const int wm = (wid >> 2) * 64;       // warp m offset
    const int wn = (wid & 3) * 32;        // warp n offset
    const int g = lane >> 2;
    const int tg = lane & 3;

    const __half* xbase = g_xh + ((size_t)(b * T_SZ + chunk * BM)) * K_IN;

    float acc[4][4][4];
#pragma unroll
    for (int mi = 0; mi < 4; mi++)
#pragma unroll
        for (int ni = 0; ni < 4; ni++)
#pragma unroll
            for (int r = 0; r < 4; r++) acc[mi][ni][r] = 0.0f;

    // ---- tile loader (cp.async, 16B granules) ----
    // A tile: 128 rows x 64 halves.  W tile: 128 n-rows x 64 halves.
    // n < 64 -> f col (g_wh row d0+n); n >= 64 -> z col (g_wh row 1024+d0+n-64).
    auto load_stage = [&](int s, int kk) {
        uint32_t abase = sb + s * STAGE;
        uint32_t wbase = abase + ABYTES;
#pragma unroll
        for (int j = 0; j < 4; j++) {
            int idx = tid + j * 256;
            int r = idx >> 3, c8 = idx & 7;
            cpa16(abase + r * (AP * 2) + c8 * 16, xbase + (size_t)r * K_IN + kk + c8 * 8);
        }
#pragma unroll
        for (int j = 0; j < 4; j++) {
            int idx = tid + j * 256;
            int n = idx >> 3, c8 = idx & 7;
            int grow = (n < 64) ? (d0 + n) : (960 + d0 + n);
            cpa16(wbase + n * (AP * 2) + c8 * 16, g_wh + (size_t)grow * K_IN + kk + c8 * 8);
        }
        CP_COMMIT();
    };

    load_stage(0, 0);

    for (int i = 0; i < NCH; i++) {
        const int s = i & 1;
        if (i + 1 < NCH) {
            load_stage(s ^ 1, (i + 1) * BK);
            CP_WAIT(1);
        } else {
            CP_WAIT(0);
        }
        __syncthreads();

        const __half* Asm = (const __half*)(smem + s * STAGE);
        const __half* Wsm = (const __half*)(smem + s * STAGE + ABYTES);

#pragma unroll
        for (int ks = 0; ks < BK / 16; ks++) {
            const int k0 = ks * 16;
            uint32_t a[4][4], bb[4][2];
#pragma unroll
            for (int mi = 0; mi < 4; mi++) {
                int r0 = wm + mi * 16;
                a[mi][0] = *(const uint32_t*)&Asm[(r0 + g) * AP + k0 + tg * 2];
                a[mi][1] = *(const uint32_t*)&Asm[(r0 + g + 8) * AP + k0 + tg * 2];
                a[mi][2] = *(const uint32_t*)&Asm[(r0 + g) * AP + k0 + 8 + tg * 2];
                a[mi][3] = *(const uint32_t*)&Asm[(r0 + g + 8) * AP + k0 + 8 + tg * 2];
            }
#pragma unroll
            for (int ni = 0; ni < 4; ni++) {
                int n = wn + ni * 8 + g;
                bb[ni][0] = *(const uint32_t*)&Wsm[n * AP + k0 + tg * 2];
                bb[ni][1] = *(const uint32_t*)&Wsm[n * AP + k0 + 8 + tg * 2];
            }
#pragma unroll
            for (int mi = 0; mi < 4; mi++)
#pragma unroll
                for (int ni = 0; ni < 4; ni++)
                    mma_f16(acc[mi][ni], a[mi][0], a[mi][1], a[mi][2], a[mi][3],
                            bb[ni][0], bb[ni][1]);
        }
        __syncthreads();
    }

    // ---- epilogue: accumulators -> smem (f | z), then chunk scan ----
    float* fS = (float*)smem;                       // [128][EPITCH]
    float* zS = (float*)smem + 128 * EPITCH;        // [128][EPITCH]
    __shared__ float sA[2][64];
    __shared__ float sC[2][64];

#pragma unroll
    for (int mi = 0; mi < 4; mi++) {
#pragma unroll
        for (int ni = 0; ni < 4; ni++) {
            int nc = wn + ni * 8 + tg * 2;          // 0..126
            float* buf = (nc < 64) ? fS : zS;
            int col = nc & 63;
            int r = wm + mi * 16 + g;
            *(float2*)&buf[r * EPITCH + col] = make_float2(acc[mi][ni][0], acc[mi][ni][1]);
            *(float2*)&buf[(r + 8) * EPITCH + col] = make_float2(acc[mi][ni][2], acc[mi][ni][3]);
        }
    }
    __syncthreads();

    {
        const int dd = tid & 63;
        const int j = tid >> 6;                      // 0..3 -> 4 t-subchunks of 32
        const float bpf = bp[d0 + dd];
        const float bpz = bp[D_MODEL + d0 + dd];
        float A = 1.0f, C = 0.0f;
#pragma unroll 4
        for (int t = j * 32; t < j * 32 + 32; t++) {
            float fh = fS[t * EPITCH + dd] + bpf;
            float zh = zS[t * EPITCH + dd] + bpz;
            float f = sigmoidf_(fh);
            float z = (1.0f - f) * tanhf(zh);
            C = C * f + z;
            A = A * f;
        }
        // fold 4 subchunks via the two smem arrays (reuse sA/sC as [4][64] pairs)
        __shared__ float s4A[4][64];
        __shared__ float s4C[4][64];
        s4A[j][dd] = A;
        s4C[j][dd] = C;
        __syncthreads();
        if (tid < 64) {
            float AA = s4A[0][tid], CC = s4C[0][tid];
#pragma unroll
            for (int jj = 1; jj < 4; jj++) {
                CC = CC * s4A[jj][tid] + s4C[jj][tid];
                AA = AA * s4A[jj][tid];
            }
            size_t o = ((size_t)b * NCHUNK + chunk) * D_MODEL + d0 + tid;
            g_chunkA[o] = AA;
            g_chunkC[o] = CC;
        }
    }
    (void)sA; (void)sC;
}

// =====================================================================
// combine chunks -> c_T
// =====================================================================
__global__ void combine_kernel() {
    int b = blockIdx.y;
    int d = blockIdx.x * 256 + threadIdx.x;
    float c = 0.0f;
#pragma unroll
    for (int ch = 0; ch < NCHUNK; ch++) {
        size_t o = ((size_t)b * NCHUNK + ch) * D_MODEL + d;
        c = c * g_chunkA[o] + g_chunkC[o];
    }
    g_cT[b * D_MODEL + d] = c;
}

// =====================================================================
// Tail: split-K vector(16) x matrix + atomicAdd
// =====================================================================
#define KS 64
__global__ void __launch_bounds__(256)
vmacc_kernel(const float* __restrict__ in, size_t inStride,
             const float* __restrict__ W, int ldw, int colOff,
             float* __restrict__ pre, int K, int N) {
    __shared__ float s_in[B_SZ * KS];
    const int tid = threadIdx.x;
    const int bn = blockIdx.x * 256;
    const int ks = blockIdx.y * KS;

    for (int i = tid; i < B_SZ * KS; i += 256) {
        int bb = i / KS, k = i % KS;
        s_in[i] = in[(size_t)bb * inStride + ks + k];
    }
    __syncthreads();

    int n = bn + tid;
    if (n >= N) return;

    float acc[B_SZ];
#pragma unroll
    for (int bb = 0; bb < B_SZ; bb++) acc[bb] = 0.0f;

    for (int k = 0; k < KS; k++) {
        float w = W[(size_t)(ks + k) * ldw + colOff + n];
#pragma unroll
        for (int bb = 0; bb < B_SZ; bb++) acc[bb] += s_in[bb * KS + k] * w;
    }
#pragma unroll
    for (int bb = 0; bb < B_SZ; bb++) atomicAdd(&pre[(size_t)bb * N + n], acc[bb]);
}

__global__ void zero_kernel() {
    int i = blockIdx.x * 256 + threadIdx.x;
    if (i < B_SZ * D_MODEL) g_opre[i] = 0.0f;
    if (i < B_SZ * MLP) { g_n0pre[i] = 0.0f; g_n1pre[i] = 0.0f; }
    if (i < B_SZ * NCLS) g_outpre[i] = 0.0f;
}

__global__ void final_oh_kernel(const float* __restrict__ bp) {
    int i = blockIdx.x * 256 + threadIdx.x;
    if (i < B_SZ * D_MODEL) {
        int d = i & (D_MODEL - 1);
        float o = 1.0f / (1.0f + __expf(-(g_opre[i] + bp[2 * D_MODEL + d])));
        g_h[i] = g_cT[i] * o;
    }
}

__global__ void final_relu0_kernel(const float* __restrict__ bias) {
    int i = blockIdx.x * 256 + threadIdx.x;
    if (i < B_SZ * MLP) {
        int n = i & (MLP - 1);
        float v = g_n0pre[i] + bias[n];
        g_n0[i] = v > 0.0f ? v : 0.0f;
    }
}

__global__ void final_relu1_kernel(const float* __restrict__ bias) {
    int i = blockIdx.x * 256 + threadIdx.x;
    if (i < B_SZ * MLP) {
        int n = i & (MLP - 1);
        float v = g_n1pre[i] + bias[n];
        g_n1[i] = v > 0.0f ? v : 0.0f;
    }
}

__global__ void final_out_kernel(const float* __restrict__ b2, float* __restrict__ out) {
    int i = blockIdx.x * 256 + threadIdx.x;
    if (i < B_SZ * NCLS) {
        int n = i % NCLS;
        out[i] = g_outpre[i] + b2[n];
    }
}

// =====================================================================
extern "C" void kernel_launch(void* const* d_in, const int* in_sizes, int n_in,
                              void* d_out, int out_size) {
    const float* x  = (const float*)d_in[0];
    const float* Wp = (const float*)d_in[1];
    const float* bp = (const float*)d_in[2];
    const float* W0 = (const float*)d_in[3];
    const float* b0 = (const float*)d_in[4];
    const float* W1 = (const float*)d_in[5];
    const float* b1 = (const float*)d_in[6];
    const float* W2 = (const float*)d_in[7];
    const float* b2 = (const float*)d_in[8];
    float* out = (float*)d_out;

    cudaFuncSetAttribute(gemm_scan_kernel,
                         cudaFuncAttributeMaxDynamicSharedMemorySize, SMEM_TOTAL);

    float *p_h, *p_n0, *p_n1, *p_opre, *p_n0pre, *p_n1pre, *p_outpre;
    cudaGetSymbolAddress((void**)&p_h, g_h);
    cudaGetSymbolAddress((void**)&p_n0, g_n0);
    cudaGetSymbolAddress((void**)&p_n1, g_n1);
    cudaGetSymbolAddress((void**)&p_opre, g_opre);
    cudaGetSymbolAddress((void**)&p_n0pre, g_n0pre);
    cudaGetSymbolAddress((void**)&p_n1pre, g_n1pre);
    cudaGetSymbolAddress((void**)&p_outpre, g_outpre);

    // 0. conversions + zeroing
    convx_kernel<<<2048, 256>>>(x);
    convw_kernel<<<dim3(K_IN / 64, 2048 / 64), 256>>>(Wp);
    zero_kernel<<<(B_SZ * MLP + 255) / 256, 256>>>();

    // 1. fused fp16 GEMM + chunk scan
    gemm_scan_kernel<<<dim3(16, B_SZ * NCHUNK), 256, SMEM_TOTAL>>>(bp);

    // 2. combine chunks -> c_T
    combine_kernel<<<dim3(D_MODEL / 256, B_SZ), 256>>>();

    // 3. o-projection at t = T-1, then h = c_T * sigmoid(oh + bp_o)
    vmacc_kernel<<<dim3(D_MODEL / 256, K_IN / KS), 256>>>(
        x + (size_t)(T_SZ - 1) * K_IN, (size_t)T_SZ * K_IN,
        Wp, 3 * D_MODEL, 2 * D_MODEL, p_opre, K_IN, D_MODEL);
    final_oh_kernel<<<(B_SZ * D_MODEL + 255) / 256, 256>>>(bp);

    // 4. MLP layer 0
    vmacc_kernel<<<dim3(MLP / 256, D_MODEL / KS), 256>>>(
        p_h, D_MODEL, W0, MLP, 0, p_n0pre, D_MODEL, MLP);
    final_relu0_kernel<<<(B_SZ * MLP + 255) / 256, 256>>>(b0);

    // 5. MLP layer 1
    vmacc_kernel<<<dim3(MLP / 256, MLP / KS), 256>>>(
        p_n0, MLP, W1, MLP, 0, p_n1pre, MLP, MLP);
    final_relu1_kernel<<<(B_SZ * MLP + 255) / 256, 256>>>(b1);

    // 6. output layer
    vmacc_kernel<<<dim3((NCLS + 255) / 256, MLP / KS), 256>>>(
        p_n1, MLP, W2, NCLS, 0, p_outpre, MLP, NCLS);
    final_out_kernel<<<(B_SZ * NCLS + 255) / 256, 256>>>(b2, out);
}